// round 9
// baseline (speedup 1.0000x reference)
#include <cuda_runtime.h>
#include <cuda_bf16.h>
#include <cstdint>

#define TT  15
#define C1I 6
#define HI  224
#define WI  224
#define C1O 30
#define HP  114
#define WP  114
#define C2O 240
#define HO  112
#define WO  112

// Layer-1 pooled spikes, channel-last bf16, padded: [t][y(114)][x(114)][32]
__device__ __align__(16) unsigned short g_spk1b[(size_t)TT * HP * WP * 32];
// Conv1 B-fragments: [s(13)][nt(4)][lane(32)] uint2 (k = tap*8+ic, N=32)
__device__ __align__(16) uint2 g_Bf1[13 * 4 * 32];
// Conv2 B-fragments: [s(18)][nh(2)][nt(15)][lane(32)] uint2 (k = tap*32+ic)
__device__ __align__(16) uint2 g_Bf2[18 * 2 * 15 * 32];

__device__ __forceinline__ uint32_t cvta_smem(const void* p) {
    uint32_t a;
    asm("{ .reg .u64 t; cvta.to.shared.u64 t, %1; cvt.u32.u64 %0, t; }"
        : "=r"(a) : "l"(p));
    return a;
}
__device__ __forceinline__ unsigned short f2bf(float f) {
    __nv_bfloat16 b = __float2bfloat16(f);
    return *(unsigned short*)&b;
}

// ---------------------------------------------------------------------------
// Prep: build bf16 B-fragments for both convs (mma.sync m16n8k16 .row.col:
// lane l holds n = l>>2, k = (l&3)*2 + r*8 + e).
// ---------------------------------------------------------------------------
__global__ __launch_bounds__(256) void k_prep(const float* __restrict__ w1,
                                              const float* __restrict__ w2) {
    int i = blockIdx.x * 256 + threadIdx.x;
    if (i < 13 * 4 * 32) {                      // conv1
        int l = i & 31, nt = (i >> 5) & 3, s = i >> 7;
        int oc = nt * 8 + (l >> 2);
        uint32_t rr[2];
#pragma unroll
        for (int r = 0; r < 2; r++) {
            uint32_t pk = 0;
#pragma unroll
            for (int e = 0; e < 2; e++) {
                int k = s * 16 + (l & 3) * 2 + r * 8 + e;
                int tap = k >> 3, ic = k & 7;
                float w = (ic < 6 && tap < 25 && oc < 30)
                        ? w1[(oc * 6 + ic) * 25 + tap] : 0.0f;
                pk |= (uint32_t)f2bf(w) << (16 * e);
            }
            rr[r] = pk;
        }
        g_Bf1[i] = make_uint2(rr[0], rr[1]);
    } else if (i < 13 * 4 * 32 + 18 * 2 * 15 * 32) {  // conv2
        int j = i - 13 * 4 * 32;
        int l = j & 31, nt = (j >> 5) % 15, nh = (j / 480) & 1, s = j / 960;
        int oc = nh * 120 + nt * 8 + (l >> 2);
        uint32_t rr[2];
#pragma unroll
        for (int r = 0; r < 2; r++) {
            uint32_t pk = 0;
#pragma unroll
            for (int e = 0; e < 2; e++) {
                int k = s * 16 + (l & 3) * 2 + r * 8 + e;
                int tap = k >> 5, ic = k & 31;
                float w = (ic < 30) ? w2[(oc * 30 + ic) * 9 + tap] : 0.0f;
                pk |= (uint32_t)f2bf(w) << (16 * e);
            }
            rr[r] = pk;
        }
        g_Bf2[j] = make_uint2(rr[0], rr[1]);
    }
}

// ---------------------------------------------------------------------------
// Kernel 1: conv1 via mma.sync + fire(15) + maxpool 2x2 -> channel-last bf16.
// CTA (256 thr, 8 warps): 16x16 conv-px tile (M=256), N=32, K=208.
// ---------------------------------------------------------------------------
#define C1_IMG   0
#define C1_C     6400
#define C1_SMEM  (6400 + 32768)

__global__ __launch_bounds__(256) void k_conv1(const float* __restrict__ in) {
    extern __shared__ __align__(16) unsigned char sm[];
    const uint32_t smb = cvta_smem(sm);
    float* sC = (float*)(sm + C1_C);           // [py16][px16][oc32]

    const int t   = blockIdx.z;
    const int X0  = blockIdx.x * 16;
    const int Y0  = blockIdx.y * 16;
    const int tid = threadIdx.x;
    const int wid = tid >> 5;
    const int l   = tid & 31;

    const float* inT = in + (size_t)t * (C1I * HI * WI);
    for (int i = tid; i < 400; i += 256) {
        int ly = i / 20, lx = i % 20;
        int gy = Y0 - 2 + ly, gx = X0 - 2 + lx;
        unsigned short row[8];
        bool ok = (unsigned)gy < (unsigned)HI && (unsigned)gx < (unsigned)WI;
#pragma unroll
        for (int ic = 0; ic < 6; ic++)
            row[ic] = ok ? f2bf(inT[(ic * HI + gy) * WI + gx]) : 0;
        row[6] = 0; row[7] = 0;
        *(uint4*)(sm + C1_IMG + i * 16) = *(uint4*)row;
    }
    __syncthreads();

    float c[2][4][4];
#pragma unroll
    for (int i = 0; i < 2; i++)
#pragma unroll
        for (int nt = 0; nt < 4; nt++)
#pragma unroll
            for (int j = 0; j < 4; j++) c[i][nt][j] = 0.0f;

    const int pxl  = l & 15;
    const int tsel = l >> 4;

    for (int s = 0; s < 13; s++) {
        int tp = 2 * s + tsel; if (tp > 24) tp = 24;   // tap25: w=0, clamp addr
        int kh = tp / 5, kw = tp - 5 * kh;
#pragma unroll
        for (int i = 0; i < 2; i++) {
            int py = 2 * wid + i;
            uint32_t addr = smb + C1_IMG + ((py + kh) * 20 + pxl + kw) * 16;
            uint32_t a0, a1, a2, a3;
            asm volatile("ldmatrix.sync.aligned.m8n8.x4.shared.b16 {%0,%1,%2,%3}, [%4];"
                         : "=r"(a0), "=r"(a1), "=r"(a2), "=r"(a3) : "r"(addr));
            const uint2* bp = g_Bf1 + s * 128 + l;
#pragma unroll
            for (int nt = 0; nt < 4; nt++) {
                uint2 b = __ldg(bp + nt * 32);
                asm volatile(
                    "mma.sync.aligned.m16n8k16.row.col.f32.bf16.bf16.f32 "
                    "{%0,%1,%2,%3}, {%4,%5,%6,%7}, {%8,%9}, {%0,%1,%2,%3};"
                    : "+f"(c[i][nt][0]), "+f"(c[i][nt][1]),
                      "+f"(c[i][nt][2]), "+f"(c[i][nt][3])
                    : "r"(a0), "r"(a1), "r"(a2), "r"(a3), "r"(b.x), "r"(b.y));
            }
        }
    }

#pragma unroll
    for (int i = 0; i < 2; i++) {
        int py = 2 * wid + i;
        int px0 = l >> 2, oc0 = 2 * (l & 3);
#pragma unroll
        for (int nt = 0; nt < 4; nt++) {
            *(float2*)(sC + (py * 16 + px0) * 32 + nt * 8 + oc0)
                = make_float2(c[i][nt][0], c[i][nt][1]);
            *(float2*)(sC + (py * 16 + px0 + 8) * 32 + nt * 8 + oc0)
                = make_float2(c[i][nt][2], c[i][nt][3]);
        }
    }
    __syncthreads();

    {
        int ocq = tid & 3;
        int ppx = (tid >> 2) & 7;
        int ppy = tid >> 5;
        uint32_t w[4];
#pragma unroll
        for (int u = 0; u < 4; u++) {
            uint32_t word = 0;
#pragma unroll
            for (int h = 0; h < 2; h++) {
                int oc = ocq * 8 + u * 2 + h;
                const float* p = sC + ((2 * ppy) * 16 + 2 * ppx) * 32 + oc;
                float m = fmaxf(fmaxf(p[0], p[32]), fmaxf(p[16 * 32], p[17 * 32]));
                if (m > 15.0f) word |= 0x3F80u << (16 * h);
            }
            w[u] = word;
        }
        int y = blockIdx.y * 8 + ppy + 1;
        int x = blockIdx.x * 8 + ppx + 1;
        *(uint4*)(g_spk1b + ((size_t)(t * HP + y) * WP + x) * 32 + ocq * 8)
            = make_uint4(w[0], w[1], w[2], w[3]);
    }
}

// ---------------------------------------------------------------------------
// Kernel 2: conv2 via mma.sync (single bf16 pass) + fire(10).
// CTA (512 thr, 16 warps): 16x8 px (M=128), N=240, K=288.
// Epilogue: stage accumulators in smem (reusing A) per nh-half, then fully
// coalesced float4 stores of spk and pot.
// ---------------------------------------------------------------------------
#define ASTR 592
#define SMA_BYTES (128 * ASTR)

__global__ __launch_bounds__(512) void k_conv2(float* __restrict__ spk,
                                               float* __restrict__ pot) {
    extern __shared__ __align__(16) unsigned char sm[];
    const uint32_t smb = cvta_smem(sm);
    const int tid = threadIdx.x;
    const int wid = tid >> 5;
    const int l   = tid & 31;

    const int t   = blockIdx.z;
    const int OY0 = blockIdx.y * 8;
    const int OX0 = blockIdx.x * 16;

    const unsigned short* spb = g_spk1b + (size_t)t * HP * WP * 32;
    for (int i = tid; i < 4608; i += 512) {
        int u = i & 3, tap = (i >> 2) % 9, m = i / 36;
        int kh = tap / 3, kw = tap - kh * 3;
        int py = m >> 4, px = m & 15;
        uint4 v = *(const uint4*)(spb +
            ((size_t)(OY0 + py + kh) * WP + (OX0 + px + kw)) * 32 + u * 8);
        *(uint4*)(sm + m * ASTR + tap * 64 + u * 16) = v;
    }
    __syncthreads();

    const int mt = wid & 7;
    const int nh = wid >> 3;

    const uint32_t abase = smb
        + (mt * 16 + ((l >> 3) & 1) * 8 + (l & 7)) * ASTR
        + ((l >> 4) & 1) * 16;

    float c[15][4];
#pragma unroll
    for (int nt = 0; nt < 15; nt++)
#pragma unroll
        for (int j = 0; j < 4; j++) c[nt][j] = 0.0f;

    for (int s = 0; s < 18; s++) {
        __syncthreads();
        uint32_t a0, a1, a2, a3;
        asm volatile("ldmatrix.sync.aligned.m8n8.x4.shared.b16 {%0,%1,%2,%3}, [%4];"
                     : "=r"(a0), "=r"(a1), "=r"(a2), "=r"(a3)
                     : "r"(abase + s * 32));
        const uint2* bp = g_Bf2 + ((s * 2 + nh) * 15) * 32 + l;
#pragma unroll
        for (int nt = 0; nt < 15; nt++) {
            uint2 b = __ldg(bp + nt * 32);
            asm volatile(
                "mma.sync.aligned.m16n8k16.row.col.f32.bf16.bf16.f32 "
                "{%0,%1,%2,%3}, {%4,%5,%6,%7}, {%8,%9}, {%0,%1,%2,%3};"
                : "+f"(c[nt][0]), "+f"(c[nt][1]), "+f"(c[nt][2]), "+f"(c[nt][3])
                : "r"(a0), "r"(a1), "r"(a2), "r"(a3), "r"(b.x), "r"(b.y));
        }
    }

    // ---- Coalesced epilogue: stage per-half C in smem, float4 stores ----
    const int g   = l >> 2;
    const int tig = l & 3;
    float* sC = (float*)sm;                       // [oc 120][m 128]
    const size_t tb = (size_t)t * C2O * HO * WO;
    const size_t n2 = (size_t)TT * C2O * HO * WO;

    for (int h = 0; h < 2; h++) {
        __syncthreads();
        if (nh == h) {
#pragma unroll
            for (int nt = 0; nt < 15; nt++)
#pragma unroll
                for (int j = 0; j < 4; j++) {
                    int ocl = nt * 8 + 2 * tig + (j & 1);
                    int m   = mt * 16 + g + ((j & 2) ? 8 : 0);
                    sC[ocl * 128 + m] = c[nt][j];
                }
        }
        __syncthreads();
        for (int f = tid; f < 3840; f += 512) {
            float4 a = ((const float4*)sC)[f];
            int ocl = f >> 5;                     // 32 float4 per oc
            int mq  = f & 31;
            int py  = mq >> 2, px0 = (mq & 3) * 4;
            size_t bi = tb + (size_t)(h * 120 + ocl) * HO * WO
                      + (size_t)(OY0 + py) * WO + OX0 + px0;
            float4 s4, p4;
            s4.x = a.x > 10.0f ? 1.0f : 0.0f;  p4.x = a.x > 10.0f ? a.x : 0.0f;
            s4.y = a.y > 10.0f ? 1.0f : 0.0f;  p4.y = a.y > 10.0f ? a.y : 0.0f;
            s4.z = a.z > 10.0f ? 1.0f : 0.0f;  p4.z = a.z > 10.0f ? a.z : 0.0f;
            s4.w = a.w > 10.0f ? 1.0f : 0.0f;  p4.w = a.w > 10.0f ? a.w : 0.0f;
            *(float4*)(spk + bi) = s4;
            *(float4*)(pot + bi) = p4;
        }
    }
    (void)n2;
}

// ---------------------------------------------------------------------------
extern "C" void kernel_launch(void* const* d_in, const int* in_sizes, int n_in,
                              void* d_out, int out_size) {
    const float* in = (const float*)d_in[0];
    const float* w1 = (const float*)d_in[1];
    const float* w2 = (const float*)d_in[2];

    float* spk = (float*)d_out;
    const size_t n2 = (size_t)TT * C2O * HO * WO;
    float* pot = spk + n2;

    void* p1 = nullptr; cudaGetSymbolAddress(&p1, g_spk1b);
    cudaMemsetAsync(p1, 0, (size_t)TT * HP * WP * 32 * 2, 0);

    cudaFuncSetAttribute(k_conv1, cudaFuncAttributeMaxDynamicSharedMemorySize, C1_SMEM);
    cudaFuncSetAttribute(k_conv2, cudaFuncAttributeMaxDynamicSharedMemorySize, SMA_BYTES);

    const int nprep = 13 * 4 * 32 + 18 * 2 * 15 * 32;
    k_prep<<<(nprep + 255) / 256, 256>>>(w1, w2);
    k_conv1<<<dim3(14, 14, TT), 256, C1_SMEM>>>(in);
    k_conv2<<<dim3(7, 14, TT), 512, SMA_BYTES>>>(spk, pot);
}

// round 10
// speedup vs baseline: 1.1512x; 1.1512x over previous
#include <cuda_runtime.h>
#include <cuda_bf16.h>
#include <cstdint>

#define TT  15
#define C1I 6
#define HI  224
#define WI  224
#define C1O 30
#define HP  114
#define WP  114
#define C2O 240
#define HO  112
#define WO  112

// Input, channel-last bf16: [t][y(224)][x(224)][8]
__device__ __align__(16) unsigned short g_inb[(size_t)TT * HI * WI * 8];
// Layer-1 pooled spikes, channel-last bf16, padded: [t][y(114)][x(114)][32]
__device__ __align__(16) unsigned short g_spk1b[(size_t)TT * HP * WP * 32];
// Conv1 B-fragments, nt-paired: [s(13)][jp(2)][lane(32)] uint4
__device__ __align__(16) uint4 g_Bf1p[13 * 2 * 32];
// Conv2 B-fragments, nt-paired: [s(18)][nh(2)][jp(8)][lane(32)] uint4
__device__ __align__(16) uint4 g_Bf2p[18 * 2 * 8 * 32];

__device__ __forceinline__ uint32_t cvta_smem(const void* p) {
    uint32_t a;
    asm("{ .reg .u64 t; cvta.to.shared.u64 t, %1; cvt.u32.u64 %0, t; }"
        : "=r"(a) : "l"(p));
    return a;
}
__device__ __forceinline__ unsigned short f2bf(float f) {
    __nv_bfloat16 b = __float2bfloat16(f);
    return *(unsigned short*)&b;
}

// ---------------------------------------------------------------------------
// Prep: B-fragments (m16n8k16 .row.col: lane l holds n=l>>2, k=(l&3)*2+r*8+e),
// packed as nt-pairs so the mainloop uses LDG.128.
// ---------------------------------------------------------------------------
__global__ __launch_bounds__(256) void k_prep(const float* __restrict__ w1,
                                              const float* __restrict__ w2) {
    int i = blockIdx.x * 256 + threadIdx.x;
    if (i < 13 * 2 * 32) {                       // conv1: k = tap*8+ic
        int l = i & 31, jp = (i >> 5) & 1, s = i >> 6;
        uint32_t q[4];
#pragma unroll
        for (int h = 0; h < 2; h++) {
            int nt = 2 * jp + h;
            int oc = nt * 8 + (l >> 2);
#pragma unroll
            for (int r = 0; r < 2; r++) {
                uint32_t pk = 0;
#pragma unroll
                for (int e = 0; e < 2; e++) {
                    int k = s * 16 + (l & 3) * 2 + r * 8 + e;
                    int tap = k >> 3, ic = k & 7;
                    float w = (ic < 6 && tap < 25 && oc < 30)
                            ? w1[(oc * 6 + ic) * 25 + tap] : 0.0f;
                    pk |= (uint32_t)f2bf(w) << (16 * e);
                }
                q[h * 2 + r] = pk;
            }
        }
        g_Bf1p[i] = make_uint4(q[0], q[1], q[2], q[3]);
    } else if (i < 13 * 2 * 32 + 18 * 2 * 8 * 32) {   // conv2: k = tap*32+ic
        int j = i - 13 * 2 * 32;
        int l = j & 31, jp = (j >> 5) & 7, nh = (j >> 8) & 1, s = j >> 9;
        uint32_t q[4] = {0, 0, 0, 0};
#pragma unroll
        for (int h = 0; h < 2; h++) {
            int nt = 2 * jp + h;
            if (nt < 15) {
                int oc = nh * 120 + nt * 8 + (l >> 2);
#pragma unroll
                for (int r = 0; r < 2; r++) {
                    uint32_t pk = 0;
#pragma unroll
                    for (int e = 0; e < 2; e++) {
                        int k = s * 16 + (l & 3) * 2 + r * 8 + e;
                        int tap = k >> 5, ic = k & 31;
                        float w = (ic < 30) ? w2[(oc * 30 + ic) * 9 + tap] : 0.0f;
                        pk |= (uint32_t)f2bf(w) << (16 * e);
                    }
                    q[h * 2 + r] = pk;
                }
            }
        }
        g_Bf2p[j] = make_uint4(q[0], q[1], q[2], q[3]);
    }
}

// ---------------------------------------------------------------------------
// Convert input NCHW f32 -> channel-last bf16 (coalesced both sides).
// ---------------------------------------------------------------------------
__global__ __launch_bounds__(256) void k_cvt(const float* __restrict__ in) {
    int p = blockIdx.x * 256 + threadIdx.x;
    if (p >= TT * HI * WI) return;
    int t  = p / (HI * WI);
    int px = p % (HI * WI);
    const float* b = in + (size_t)t * C1I * HI * WI + px;
    unsigned short r[8];
#pragma unroll
    for (int ic = 0; ic < 6; ic++) r[ic] = f2bf(b[(size_t)ic * HI * WI]);
    r[6] = 0; r[7] = 0;
    *(uint4*)(g_inb + (size_t)p * 8) = *(uint4*)r;
}

// ---------------------------------------------------------------------------
// Kernel 1: conv1 via mma.sync + fire(15) + maxpool 2x2 -> channel-last bf16.
// CTA (256 thr, 8 warps): 16x16 conv-px tile (M=256), N=32, K=208.
// ---------------------------------------------------------------------------
#define C1_IMG   0
#define C1_C     6400
#define C1_SMEM  (6400 + 32768)

__global__ __launch_bounds__(256) void k_conv1() {
    extern __shared__ __align__(16) unsigned char sm[];
    const uint32_t smb = cvta_smem(sm);
    float* sC = (float*)(sm + C1_C);           // [py16][px16][oc32]

    const int t   = blockIdx.z;
    const int X0  = blockIdx.x * 16;
    const int Y0  = blockIdx.y * 16;
    const int tid = threadIdx.x;
    const int wid = tid >> 5;
    const int l   = tid & 31;

    // Halo image [20][20][8] bf16 from pre-converted input (16B loads)
    const unsigned short* inb = g_inb + (size_t)t * HI * WI * 8;
    for (int i = tid; i < 400; i += 256) {
        int ly = i / 20, lx = i % 20;
        int gy = Y0 - 2 + ly, gx = X0 - 2 + lx;
        uint4 v = make_uint4(0, 0, 0, 0);
        if ((unsigned)gy < (unsigned)HI && (unsigned)gx < (unsigned)WI)
            v = *(const uint4*)(inb + ((size_t)gy * WI + gx) * 8);
        *(uint4*)(sm + C1_IMG + i * 16) = v;
    }
    __syncthreads();

    float c[2][4][4];
#pragma unroll
    for (int i = 0; i < 2; i++)
#pragma unroll
        for (int nt = 0; nt < 4; nt++)
#pragma unroll
            for (int j = 0; j < 4; j++) c[i][nt][j] = 0.0f;

    const int pxl  = l & 15;
    const int tsel = l >> 4;

    for (int s = 0; s < 13; s++) {
        int tp = 2 * s + tsel; if (tp > 24) tp = 24;   // tap25: w=0, clamp addr
        int kh = tp / 5, kw = tp - 5 * kh;
#pragma unroll
        for (int i = 0; i < 2; i++) {
            int py = 2 * wid + i;
            uint32_t addr = smb + C1_IMG + ((py + kh) * 20 + pxl + kw) * 16;
            uint32_t a0, a1, a2, a3;
            asm volatile("ldmatrix.sync.aligned.m8n8.x4.shared.b16 {%0,%1,%2,%3}, [%4];"
                         : "=r"(a0), "=r"(a1), "=r"(a2), "=r"(a3) : "r"(addr));
            const uint4* bp = g_Bf1p + s * 64 + l;
#pragma unroll
            for (int jp = 0; jp < 2; jp++) {
                uint4 b = __ldg(bp + jp * 32);
                asm volatile(
                    "mma.sync.aligned.m16n8k16.row.col.f32.bf16.bf16.f32 "
                    "{%0,%1,%2,%3}, {%4,%5,%6,%7}, {%8,%9}, {%0,%1,%2,%3};"
                    : "+f"(c[i][2*jp][0]), "+f"(c[i][2*jp][1]),
                      "+f"(c[i][2*jp][2]), "+f"(c[i][2*jp][3])
                    : "r"(a0), "r"(a1), "r"(a2), "r"(a3), "r"(b.x), "r"(b.y));
                asm volatile(
                    "mma.sync.aligned.m16n8k16.row.col.f32.bf16.bf16.f32 "
                    "{%0,%1,%2,%3}, {%4,%5,%6,%7}, {%8,%9}, {%0,%1,%2,%3};"
                    : "+f"(c[i][2*jp+1][0]), "+f"(c[i][2*jp+1][1]),
                      "+f"(c[i][2*jp+1][2]), "+f"(c[i][2*jp+1][3])
                    : "r"(a0), "r"(a1), "r"(a2), "r"(a3), "r"(b.z), "r"(b.w));
            }
        }
    }

#pragma unroll
    for (int i = 0; i < 2; i++) {
        int py = 2 * wid + i;
        int px0 = l >> 2, oc0 = 2 * (l & 3);
#pragma unroll
        for (int nt = 0; nt < 4; nt++) {
            *(float2*)(sC + (py * 16 + px0) * 32 + nt * 8 + oc0)
                = make_float2(c[i][nt][0], c[i][nt][1]);
            *(float2*)(sC + (py * 16 + px0 + 8) * 32 + nt * 8 + oc0)
                = make_float2(c[i][nt][2], c[i][nt][3]);
        }
    }
    __syncthreads();

    {
        int ocq = tid & 3;
        int ppx = (tid >> 2) & 7;
        int ppy = tid >> 5;
        uint32_t w[4];
#pragma unroll
        for (int u = 0; u < 4; u++) {
            uint32_t word = 0;
#pragma unroll
            for (int h = 0; h < 2; h++) {
                int oc = ocq * 8 + u * 2 + h;
                const float* p = sC + ((2 * ppy) * 16 + 2 * ppx) * 32 + oc;
                float m = fmaxf(fmaxf(p[0], p[32]), fmaxf(p[16 * 32], p[17 * 32]));
                if (m > 15.0f) word |= 0x3F80u << (16 * h);
            }
            w[u] = word;
        }
        int y = blockIdx.y * 8 + ppy + 1;
        int x = blockIdx.x * 8 + ppx + 1;
        *(uint4*)(g_spk1b + ((size_t)(t * HP + y) * WP + x) * 32 + ocq * 8)
            = make_uint4(w[0], w[1], w[2], w[3]);
    }
}

// ---------------------------------------------------------------------------
// Kernel 2: conv2 via mma.sync + fire(10). CTA (512 thr): 16x8 px, N=240.
// B loads nt-paired (LDG.128); no per-step barrier; scattered epilogue (R8).
// ---------------------------------------------------------------------------
#define ASTR 592
#define SMA_BYTES (128 * ASTR)

__global__ __launch_bounds__(512) void k_conv2(float* __restrict__ spk,
                                               float* __restrict__ pot) {
    extern __shared__ __align__(16) unsigned char sm[];
    const uint32_t smb = cvta_smem(sm);
    const int tid = threadIdx.x;
    const int wid = tid >> 5;
    const int l   = tid & 31;

    const int t   = blockIdx.z;
    const int OY0 = blockIdx.y * 8;
    const int OX0 = blockIdx.x * 16;

    const unsigned short* spb = g_spk1b + (size_t)t * HP * WP * 32;
    for (int i = tid; i < 4608; i += 512) {
        int u = i & 3, tap = (i >> 2) % 9, m = i / 36;
        int kh = tap / 3, kw = tap - kh * 3;
        int py = m >> 4, px = m & 15;
        uint4 v = *(const uint4*)(spb +
            ((size_t)(OY0 + py + kh) * WP + (OX0 + px + kw)) * 32 + u * 8);
        *(uint4*)(sm + m * ASTR + tap * 64 + u * 16) = v;
    }
    __syncthreads();

    const int mt = wid & 7;
    const int nh = wid >> 3;

    const uint32_t abase = smb
        + (mt * 16 + ((l >> 3) & 1) * 8 + (l & 7)) * ASTR
        + ((l >> 4) & 1) * 16;

    float c[15][4];
#pragma unroll
    for (int nt = 0; nt < 15; nt++)
#pragma unroll
        for (int j = 0; j < 4; j++) c[nt][j] = 0.0f;

    for (int s = 0; s < 18; s++) {
        uint32_t a0, a1, a2, a3;
        asm volatile("ldmatrix.sync.aligned.m8n8.x4.shared.b16 {%0,%1,%2,%3}, [%4];"
                     : "=r"(a0), "=r"(a1), "=r"(a2), "=r"(a3)
                     : "r"(abase + s * 32));
        const uint4* bp = g_Bf2p + ((s * 2 + nh) * 8) * 32 + l;
#pragma unroll
        for (int jp = 0; jp < 8; jp++) {
            uint4 b = __ldg(bp + jp * 32);
            asm volatile(
                "mma.sync.aligned.m16n8k16.row.col.f32.bf16.bf16.f32 "
                "{%0,%1,%2,%3}, {%4,%5,%6,%7}, {%8,%9}, {%0,%1,%2,%3};"
                : "+f"(c[2*jp][0]), "+f"(c[2*jp][1]),
                  "+f"(c[2*jp][2]), "+f"(c[2*jp][3])
                : "r"(a0), "r"(a1), "r"(a2), "r"(a3), "r"(b.x), "r"(b.y));
            if (jp < 7) {
                asm volatile(
                    "mma.sync.aligned.m16n8k16.row.col.f32.bf16.bf16.f32 "
                    "{%0,%1,%2,%3}, {%4,%5,%6,%7}, {%8,%9}, {%0,%1,%2,%3};"
                    : "+f"(c[2*jp+1][0]), "+f"(c[2*jp+1][1]),
                      "+f"(c[2*jp+1][2]), "+f"(c[2*jp+1][3])
                    : "r"(a0), "r"(a1), "r"(a2), "r"(a3), "r"(b.z), "r"(b.w));
            }
        }
    }

    const int g   = l >> 2;
    const int tig = l & 3;
    const int m0  = mt * 16 + g;
    const int m1  = m0 + 8;
    const int y0  = OY0 + (m0 >> 4), x0 = OX0 + (m0 & 15);
    const int y1  = OY0 + (m1 >> 4), x1 = OX0 + (m1 & 15);
    const size_t tb = (size_t)t * C2O * HO * WO;
    const size_t n2 = (size_t)TT * C2O * HO * WO;

#pragma unroll
    for (int nt = 0; nt < 15; nt++) {
        int oc0 = nh * 120 + nt * 8 + 2 * tig;
#pragma unroll
        for (int j = 0; j < 4; j++) {
            int   oc = oc0 + (j & 1);
            int   yy = (j < 2) ? y0 : y1;
            int   xx = (j < 2) ? x0 : x1;
            float a  = c[nt][j];
            size_t bi = tb + ((size_t)oc * HO + yy) * WO + xx;
            spk[bi]      = a > 10.0f ? 1.0f : 0.0f;
            spk[bi + n2] = a > 10.0f ? a : 0.0f;
        }
    }
}

// ---------------------------------------------------------------------------
extern "C" void kernel_launch(void* const* d_in, const int* in_sizes, int n_in,
                              void* d_out, int out_size) {
    const float* in = (const float*)d_in[0];
    const float* w1 = (const float*)d_in[1];
    const float* w2 = (const float*)d_in[2];

    float* spk = (float*)d_out;
    const size_t n2 = (size_t)TT * C2O * HO * WO;
    float* pot = spk + n2;

    void* p1 = nullptr; cudaGetSymbolAddress(&p1, g_spk1b);
    cudaMemsetAsync(p1, 0, (size_t)TT * HP * WP * 32 * 2, 0);

    cudaFuncSetAttribute(k_conv1, cudaFuncAttributeMaxDynamicSharedMemorySize, C1_SMEM);
    cudaFuncSetAttribute(k_conv2, cudaFuncAttributeMaxDynamicSharedMemorySize, SMA_BYTES);

    const int nprep = 13 * 2 * 32 + 18 * 2 * 8 * 32;
    k_prep<<<(nprep + 255) / 256, 256>>>(w1, w2);
    k_cvt<<<(TT * HI * WI + 255) / 256, 256>>>(in);
    k_conv1<<<dim3(14, 14, TT), 256, C1_SMEM>>>();
    k_conv2<<<dim3(7, 14, TT), 512, SMA_BYTES>>>(spk, pot);
}

// round 11
// speedup vs baseline: 1.3119x; 1.1396x over previous
#include <cuda_runtime.h>
#include <cuda_bf16.h>
#include <cstdint>

#define TT  15
#define C1I 6
#define HI  224
#define WI  224
#define C1O 30
#define HP  114
#define WP  114
#define C2O 240
#define HO  112
#define WO  112

// Input, channel-last bf16: [t][y(224)][x(224)][8]
__device__ __align__(16) unsigned short g_inb[(size_t)TT * HI * WI * 8];
// Layer-1 pooled spikes, channel-last bf16, padded: [t][y(114)][x(114)][32]
__device__ __align__(16) unsigned short g_spk1b[(size_t)TT * HP * WP * 32];
// Conv1 B-fragments, nt-paired: [s(13)][jp(2)][lane(32)] uint4
__device__ __align__(16) uint4 g_Bf1p[13 * 2 * 32];
// Conv2 B-fragments, nt-paired: [s(18)][nh(2)][jp(8)][lane(32)] uint4
__device__ __align__(16) uint4 g_Bf2p[18 * 2 * 8 * 32];

__device__ __forceinline__ uint32_t cvta_smem(const void* p) {
    uint32_t a;
    asm("{ .reg .u64 t; cvta.to.shared.u64 t, %1; cvt.u32.u64 %0, t; }"
        : "=r"(a) : "l"(p));
    return a;
}
__device__ __forceinline__ unsigned short f2bf(float f) {
    __nv_bfloat16 b = __float2bfloat16(f);
    return *(unsigned short*)&b;
}

#define CP16(dst, src) \
    asm volatile("cp.async.cg.shared.global [%0], [%1], 16;" \
                 :: "r"(dst), "l"(src) : "memory")
#define CP16Z(dst, src, sz) \
    asm volatile("cp.async.cg.shared.global [%0], [%1], 16, %2;" \
                 :: "r"(dst), "l"(src), "r"(sz) : "memory")
#define CP_COMMIT() asm volatile("cp.async.commit_group;" ::: "memory")
#define CP_WAIT(n)  asm volatile("cp.async.wait_group %0;" :: "n"(n) : "memory")

// ---------------------------------------------------------------------------
// Prep: B-fragments (m16n8k16 .row.col), packed as nt-pairs (LDG/LDS.128).
// ---------------------------------------------------------------------------
__global__ __launch_bounds__(256) void k_prep(const float* __restrict__ w1,
                                              const float* __restrict__ w2) {
    int i = blockIdx.x * 256 + threadIdx.x;
    if (i < 13 * 2 * 32) {                       // conv1: k = tap*8+ic
        int l = i & 31, jp = (i >> 5) & 1, s = i >> 6;
        uint32_t q[4];
#pragma unroll
        for (int h = 0; h < 2; h++) {
            int nt = 2 * jp + h;
            int oc = nt * 8 + (l >> 2);
#pragma unroll
            for (int r = 0; r < 2; r++) {
                uint32_t pk = 0;
#pragma unroll
                for (int e = 0; e < 2; e++) {
                    int k = s * 16 + (l & 3) * 2 + r * 8 + e;
                    int tap = k >> 3, ic = k & 7;
                    float w = (ic < 6 && tap < 25 && oc < 30)
                            ? w1[(oc * 6 + ic) * 25 + tap] : 0.0f;
                    pk |= (uint32_t)f2bf(w) << (16 * e);
                }
                q[h * 2 + r] = pk;
            }
        }
        g_Bf1p[i] = make_uint4(q[0], q[1], q[2], q[3]);
    } else if (i < 13 * 2 * 32 + 18 * 2 * 8 * 32) {   // conv2: k = tap*32+ic
        int j = i - 13 * 2 * 32;
        int l = j & 31, jp = (j >> 5) & 7, nh = (j >> 8) & 1, s = j >> 9;
        uint32_t q[4] = {0, 0, 0, 0};
#pragma unroll
        for (int h = 0; h < 2; h++) {
            int nt = 2 * jp + h;
            if (nt < 15) {
                int oc = nh * 120 + nt * 8 + (l >> 2);
#pragma unroll
                for (int r = 0; r < 2; r++) {
                    uint32_t pk = 0;
#pragma unroll
                    for (int e = 0; e < 2; e++) {
                        int k = s * 16 + (l & 3) * 2 + r * 8 + e;
                        int tap = k >> 5, ic = k & 31;
                        float w = (ic < 30) ? w2[(oc * 30 + ic) * 9 + tap] : 0.0f;
                        pk |= (uint32_t)f2bf(w) << (16 * e);
                    }
                    q[h * 2 + r] = pk;
                }
            }
        }
        g_Bf2p[j] = make_uint4(q[0], q[1], q[2], q[3]);
    }
}

// ---------------------------------------------------------------------------
// Convert input NCHW f32 -> channel-last bf16 (coalesced both sides).
// ---------------------------------------------------------------------------
__global__ __launch_bounds__(256) void k_cvt(const float* __restrict__ in) {
    int p = blockIdx.x * 256 + threadIdx.x;
    if (p >= TT * HI * WI) return;
    int t  = p / (HI * WI);
    int px = p % (HI * WI);
    const float* b = in + (size_t)t * C1I * HI * WI + px;
    unsigned short r[8];
#pragma unroll
    for (int ic = 0; ic < 6; ic++) r[ic] = f2bf(b[(size_t)ic * HI * WI]);
    r[6] = 0; r[7] = 0;
    *(uint4*)(g_inb + (size_t)p * 8) = *(uint4*)r;
}

// ---------------------------------------------------------------------------
// Kernel 1: conv1 via mma.sync + fire(15) + maxpool 2x2 -> channel-last bf16.
// CTA (256 thr, 8 warps): 16x16 conv-px tile (M=256), N=32, K=208.
// ---------------------------------------------------------------------------
#define C1_IMG   0
#define C1_C     6400
#define C1_SMEM  (6400 + 32768)

__global__ __launch_bounds__(256) void k_conv1() {
    extern __shared__ __align__(16) unsigned char sm[];
    const uint32_t smb = cvta_smem(sm);
    float* sC = (float*)(sm + C1_C);           // [py16][px16][oc32]

    const int t   = blockIdx.z;
    const int X0  = blockIdx.x * 16;
    const int Y0  = blockIdx.y * 16;
    const int tid = threadIdx.x;
    const int wid = tid >> 5;
    const int l   = tid & 31;

    // Halo image [20][20][8] bf16; cp.async with zero-fill for OOB
    const unsigned short* inb = g_inb + (size_t)t * HI * WI * 8;
    for (int i = tid; i < 400; i += 256) {
        int ly = i / 20, lx = i % 20;
        int gy = Y0 - 2 + ly, gx = X0 - 2 + lx;
        bool ok = (unsigned)gy < (unsigned)HI && (unsigned)gx < (unsigned)WI;
        int cy = ok ? gy : 0, cx = ok ? gx : 0;
        const unsigned short* src = inb + ((size_t)cy * WI + cx) * 8;
        CP16Z(smb + C1_IMG + i * 16, src, ok ? 16 : 0);
    }
    CP_COMMIT();
    CP_WAIT(0);
    __syncthreads();

    float c[2][4][4];
#pragma unroll
    for (int i = 0; i < 2; i++)
#pragma unroll
        for (int nt = 0; nt < 4; nt++)
#pragma unroll
            for (int j = 0; j < 4; j++) c[i][nt][j] = 0.0f;

    const int pxl  = l & 15;
    const int tsel = l >> 4;

    for (int s = 0; s < 13; s++) {
        int tp = 2 * s + tsel; if (tp > 24) tp = 24;   // tap25: w=0, clamp addr
        int kh = tp / 5, kw = tp - 5 * kh;
#pragma unroll
        for (int i = 0; i < 2; i++) {
            int py = 2 * wid + i;
            uint32_t addr = smb + C1_IMG + ((py + kh) * 20 + pxl + kw) * 16;
            uint32_t a0, a1, a2, a3;
            asm volatile("ldmatrix.sync.aligned.m8n8.x4.shared.b16 {%0,%1,%2,%3}, [%4];"
                         : "=r"(a0), "=r"(a1), "=r"(a2), "=r"(a3) : "r"(addr));
            const uint4* bp = g_Bf1p + s * 64 + l;
#pragma unroll
            for (int jp = 0; jp < 2; jp++) {
                uint4 b = __ldg(bp + jp * 32);
                asm volatile(
                    "mma.sync.aligned.m16n8k16.row.col.f32.bf16.bf16.f32 "
                    "{%0,%1,%2,%3}, {%4,%5,%6,%7}, {%8,%9}, {%0,%1,%2,%3};"
                    : "+f"(c[i][2*jp][0]), "+f"(c[i][2*jp][1]),
                      "+f"(c[i][2*jp][2]), "+f"(c[i][2*jp][3])
                    : "r"(a0), "r"(a1), "r"(a2), "r"(a3), "r"(b.x), "r"(b.y));
                asm volatile(
                    "mma.sync.aligned.m16n8k16.row.col.f32.bf16.bf16.f32 "
                    "{%0,%1,%2,%3}, {%4,%5,%6,%7}, {%8,%9}, {%0,%1,%2,%3};"
                    : "+f"(c[i][2*jp+1][0]), "+f"(c[i][2*jp+1][1]),
                      "+f"(c[i][2*jp+1][2]), "+f"(c[i][2*jp+1][3])
                    : "r"(a0), "r"(a1), "r"(a2), "r"(a3), "r"(b.z), "r"(b.w));
            }
        }
    }

#pragma unroll
    for (int i = 0; i < 2; i++) {
        int py = 2 * wid + i;
        int px0 = l >> 2, oc0 = 2 * (l & 3);
#pragma unroll
        for (int nt = 0; nt < 4; nt++) {
            *(float2*)(sC + (py * 16 + px0) * 32 + nt * 8 + oc0)
                = make_float2(c[i][nt][0], c[i][nt][1]);
            *(float2*)(sC + (py * 16 + px0 + 8) * 32 + nt * 8 + oc0)
                = make_float2(c[i][nt][2], c[i][nt][3]);
        }
    }
    __syncthreads();

    {
        int ocq = tid & 3;
        int ppx = (tid >> 2) & 7;
        int ppy = tid >> 5;
        uint32_t w[4];
#pragma unroll
        for (int u = 0; u < 4; u++) {
            uint32_t word = 0;
#pragma unroll
            for (int h = 0; h < 2; h++) {
                int oc = ocq * 8 + u * 2 + h;
                const float* p = sC + ((2 * ppy) * 16 + 2 * ppx) * 32 + oc;
                float m = fmaxf(fmaxf(p[0], p[32]), fmaxf(p[16 * 32], p[17 * 32]));
                if (m > 15.0f) word |= 0x3F80u << (16 * h);
            }
            w[u] = word;
        }
        int y = blockIdx.y * 8 + ppy + 1;
        int x = blockIdx.x * 8 + ppx + 1;
        *(uint4*)(g_spk1b + ((size_t)(t * HP + y) * WP + x) * 32 + ocq * 8)
            = make_uint4(w[0], w[1], w[2], w[3]);
    }
}

// ---------------------------------------------------------------------------
// Kernel 2: conv2 via mma.sync + fire(10). CTA (512 thr): 16x8 px, N=240.
// A: cp.async im2col build. B: 3-stage cp.async smem pipeline (prefetch
// 2 steps ahead); mma operands via conflict-free LDS.128.
// ---------------------------------------------------------------------------
#define ASTR   592
#define SB_OFF (128 * ASTR)            // 75776
#define SB_STG 8192
#define SMA_BYTES (SB_OFF + 3 * SB_STG)

__global__ __launch_bounds__(512) void k_conv2(float* __restrict__ spk,
                                               float* __restrict__ pot) {
    extern __shared__ __align__(16) unsigned char sm[];
    const uint32_t smb = cvta_smem(sm);
    const int tid = threadIdx.x;
    const int wid = tid >> 5;
    const int l   = tid & 31;

    const int t   = blockIdx.z;
    const int OY0 = blockIdx.y * 8;
    const int OX0 = blockIdx.x * 16;

    // ---- A build via cp.async (9 x 16B per thread) ----
    const unsigned short* spb = g_spk1b + (size_t)t * HP * WP * 32;
    for (int i = tid; i < 4608; i += 512) {
        int u = i & 3, tap = (i >> 2) % 9, m = i / 36;
        int kh = tap / 3, kw = tap - kh * 3;
        int py = m >> 4, px = m & 15;
        const unsigned short* src = spb +
            ((size_t)(OY0 + py + kh) * WP + (OX0 + px + kw)) * 32 + u * 8;
        CP16(smb + m * ASTR + tap * 64 + u * 16, src);
    }

    // ---- B prologue: stage 0 (group with A) and stage 1 ----
    const int bnh = tid >> 8;                 // this thread's load slot
    const int bjp = (tid >> 5) & 7;
    const int bl  = tid & 31;
    const uint4* bsrc0 = g_Bf2p + ((size_t)bnh * 8 + bjp) * 32 + bl;
    const uint32_t bdst = smb + SB_OFF + tid * 16;

    CP16(bdst, bsrc0);                        // s = 0 -> stage 0
    CP_COMMIT();                              // g0 = A + B0
    CP16(bdst + SB_STG, bsrc0 + 512);         // s = 1 -> stage 1 (+2*8*32)
    CP_COMMIT();                              // g1 = B1

    const int mt = wid & 7;
    const int nh = wid >> 3;

    const uint32_t abase = smb
        + (mt * 16 + ((l >> 3) & 1) * 8 + (l & 7)) * ASTR
        + ((l >> 4) & 1) * 16;
    const uint32_t bbase = smb + SB_OFF + (nh * 8 * 32 + l) * 16;

    float c[15][4];
#pragma unroll
    for (int nt = 0; nt < 15; nt++)
#pragma unroll
        for (int j = 0; j < 4; j++) c[nt][j] = 0.0f;

    int stage = 0;
    for (int s = 0; s < 18; s++) {
        if (s < 17) { CP_WAIT(1); } else { CP_WAIT(0); }
        __syncthreads();
        // prefetch s+2 into stage (s+2)%3 (free: all consumed s-1 already)
        if (s + 2 < 18) {
            int st2 = stage + 2; if (st2 >= 3) st2 -= 3;
            CP16(bdst + st2 * SB_STG, bsrc0 + (size_t)(s + 2) * 512);
            CP_COMMIT();
        }

        uint32_t a0, a1, a2, a3;
        asm volatile("ldmatrix.sync.aligned.m8n8.x4.shared.b16 {%0,%1,%2,%3}, [%4];"
                     : "=r"(a0), "=r"(a1), "=r"(a2), "=r"(a3)
                     : "r"(abase + s * 32));
        const uint32_t bs = bbase + stage * SB_STG;
#pragma unroll
        for (int jp = 0; jp < 8; jp++) {
            uint4 b = *(const uint4*)(sm + (bs - smb) + jp * 512);
            asm volatile(
                "mma.sync.aligned.m16n8k16.row.col.f32.bf16.bf16.f32 "
                "{%0,%1,%2,%3}, {%4,%5,%6,%7}, {%8,%9}, {%0,%1,%2,%3};"
                : "+f"(c[2*jp][0]), "+f"(c[2*jp][1]),
                  "+f"(c[2*jp][2]), "+f"(c[2*jp][3])
                : "r"(a0), "r"(a1), "r"(a2), "r"(a3), "r"(b.x), "r"(b.y));
            if (jp < 7) {
                asm volatile(
                    "mma.sync.aligned.m16n8k16.row.col.f32.bf16.bf16.f32 "
                    "{%0,%1,%2,%3}, {%4,%5,%6,%7}, {%8,%9}, {%0,%1,%2,%3};"
                    : "+f"(c[2*jp+1][0]), "+f"(c[2*jp+1][1]),
                      "+f"(c[2*jp+1][2]), "+f"(c[2*jp+1][3])
                    : "r"(a0), "r"(a1), "r"(a2), "r"(a3), "r"(b.z), "r"(b.w));
            }
        }
        stage++; if (stage == 3) stage = 0;
    }

    const int g   = l >> 2;
    const int tig = l & 3;
    const int m0  = mt * 16 + g;
    const int m1  = m0 + 8;
    const int y0  = OY0 + (m0 >> 4), x0 = OX0 + (m0 & 15);
    const int y1  = OY0 + (m1 >> 4), x1 = OX0 + (m1 & 15);
    const size_t tb = (size_t)t * C2O * HO * WO;
    const size_t n2 = (size_t)TT * C2O * HO * WO;

#pragma unroll
    for (int nt = 0; nt < 15; nt++) {
        int oc0 = nh * 120 + nt * 8 + 2 * tig;
#pragma unroll
        for (int j = 0; j < 4; j++) {
            int   oc = oc0 + (j & 1);
            int   yy = (j < 2) ? y0 : y1;
            int   xx = (j < 2) ? x0 : x1;
            float a  = c[nt][j];
            size_t bi = tb + ((size_t)oc * HO + yy) * WO + xx;
            spk[bi]      = a > 10.0f ? 1.0f : 0.0f;
            spk[bi + n2] = a > 10.0f ? a : 0.0f;
        }
    }
}

// ---------------------------------------------------------------------------
extern "C" void kernel_launch(void* const* d_in, const int* in_sizes, int n_in,
                              void* d_out, int out_size) {
    const float* in = (const float*)d_in[0];
    const float* w1 = (const float*)d_in[1];
    const float* w2 = (const float*)d_in[2];

    float* spk = (float*)d_out;
    const size_t n2 = (size_t)TT * C2O * HO * WO;
    float* pot = spk + n2;

    void* p1 = nullptr; cudaGetSymbolAddress(&p1, g_spk1b);
    cudaMemsetAsync(p1, 0, (size_t)TT * HP * WP * 32 * 2, 0);

    cudaFuncSetAttribute(k_conv1, cudaFuncAttributeMaxDynamicSharedMemorySize, C1_SMEM);
    cudaFuncSetAttribute(k_conv2, cudaFuncAttributeMaxDynamicSharedMemorySize, SMA_BYTES);

    const int nprep = 13 * 2 * 32 + 18 * 2 * 8 * 32;
    k_prep<<<(nprep + 255) / 256, 256>>>(w1, w2);
    k_cvt<<<(TT * HI * WI + 255) / 256, 256>>>(in);
    k_conv1<<<dim3(14, 14, TT), 256, C1_SMEM>>>();
    k_conv2<<<dim3(7, 14, TT), 512, SMA_BYTES>>>(spk, pot);
}